// round 12
// baseline (speedup 1.0000x reference)
#include <cuda_runtime.h>
#include <stdint.h>
#include <math.h>

#define N_AA   20
#define NB     21                        // histogram side (incl. gap symbol)
#define NSEQ   2048
#define SLEN   512
#define MPOS   100
#define NPAIR  (MPOS * (MPOS - 1) / 2)   // 4950 packed upper-triangle pairs
#define NWORK  (NPAIR + SLEN)            // + 512 stats/zero-fill items
#define GRID   1024                      // co-resident by construction (<=152*8)

// Scratch (allocation-free rule: __device__ globals)
__device__ uint8_t g_msaT[SLEN * NSEQ];       // 1 MB, transposed msa as u8
__device__ float   g_log2tab[NSEQ + 1];       // log2(c) for integer counts
__device__ unsigned int g_bar = 0;            // monotonic grid barrier (replay-safe)

__global__ void __launch_bounds__(256, 8)
k_all(const int* __restrict__ msa, const float* __restrict__ pc,
      float* __restrict__ out_pssm, float* __restrict__ out_cons,
      float* __restrict__ out_mi)
{
    __shared__ uint8_t tile[32][33];
    __shared__ int     hist[NB * NB];
    __shared__ float   warp_red[8];
    __shared__ int     sh_tot;

    int tid = threadIdx.x;
    int bx  = blockIdx.x;
    int lane = tid & 31;
    int wid  = tid >> 5;

    // ================= phase 1: transpose one 32x32 tile + log2 table ======
    {
        int i0 = (bx & 15) * 32;          // 16 tiles along i (SLEN/32)
        int n0 = (bx >> 4) * 32;          // 64 tiles along n (NSEQ/32)
        int tx = lane, ty = wid;          // 8 rows per iteration
        #pragma unroll
        for (int r = 0; r < 4; r++) {
            int row = ty + r * 8;
            tile[row][tx] = (uint8_t)msa[(n0 + row) * SLEN + (i0 + tx)];
        }
        __syncthreads();
        #pragma unroll
        for (int r = 0; r < 4; r++) {
            int row = ty + r * 8;
            g_msaT[(size_t)(i0 + row) * NSEQ + (n0 + tx)] = tile[tx][row];
        }
        if (bx < 9) {
            int idx = bx * 256 + tid;
            if (idx <= NSEQ) g_log2tab[idx] = (idx == 0) ? 0.0f : log2f((float)idx);
        }
    }

    // ================= grid-wide barrier (monotonic, replay-safe) ===========
    __threadfence();
    __syncthreads();
    if (tid == 0) {
        unsigned my     = atomicAdd(&g_bar, 1u);
        unsigned target = (my / GRID + 1u) * GRID;
        for (;;) {
            unsigned cur;
            asm volatile("ld.acquire.gpu.u32 %0, [%1];" : "=r"(cur) : "l"(&g_bar));
            if (cur >= target) break;
            __nanosleep(64);
        }
    }
    __syncthreads();

    // ================= phase 2: persistent work loop ========================
    for (int w = bx; w < NWORK; w += GRID) {
        __syncthreads();   // protect smem reuse across iterations

        if (w >= NPAIR) {
            // ------------- stats + zero-fill role: position r ---------------
            int r = w - NPAIR;

            int     c0   = (r < MPOS) ? MPOS : 0;
            float4* rowp = (float4*)(out_mi + r * SLEN + c0);
            int     n4   = (SLEN - c0) >> 2;
            float4  z4   = make_float4(0.f, 0.f, 0.f, 0.f);
            for (int k = tid; k < n4; k += 256) rowp[k] = z4;
            if (tid == 0 && r < MPOS) out_mi[r * SLEN + r] = 0.0f;

            if (tid < NB) hist[tid] = 0;
            __syncthreads();

            const uint2* col = (const uint2*)&g_msaT[(size_t)r * NSEQ];
            uint2 v = col[tid];
            #pragma unroll
            for (int b = 0; b < 4; b++) atomicAdd(&hist[(v.x >> (8 * b)) & 0xFF], 1);
            #pragma unroll
            for (int b = 0; b < 4; b++) atomicAdd(&hist[(v.y >> (8 * b)) & 0xFF], 1);
            __syncthreads();

            if (tid < 32) {
                int c   = (tid < N_AA) ? hist[tid] : 0;
                int tot = c;
                #pragma unroll
                for (int off = 16; off; off >>= 1)
                    tot += __shfl_xor_sync(0xFFFFFFFFu, tot, off);

                float e = 0.0f;
                if (tid < N_AA) {
                    float pcv  = 0.01f * pc[0];
                    float cf   = (float)c;
                    float freq = (cf + pcv) / ((float)NSEQ + pcv * (float)N_AA);
                    out_pssm[r * N_AA + tid] = logf(freq * (float)N_AA + 1e-10f);
                    float f = cf / fmaxf((float)tot, 1.0f);
                    e = f * log2f(f + 1e-10f);
                }
                #pragma unroll
                for (int off = 16; off; off >>= 1)
                    e += __shfl_xor_sync(0xFFFFFFFFu, e, off);
                if (tid == 0)
                    out_cons[r] = (tot > 0) ? (1.0f + e / 4.321928094887363f) : 0.0f;
            }
            continue;
        }

        // ------------- MI pair role: decode packed upper-triangle -----------
        int t = w;
        int i = (int)((2.0f * MPOS - 1.0f
                       - sqrtf((2.0f * MPOS - 1.0f) * (2.0f * MPOS - 1.0f)
                               - 8.0f * (float)t)) * 0.5f);
        while (i > 0 && t <  (i * (2 * MPOS - 1 - i)) / 2) i--;
        while (t >= ((i + 1) * (2 * MPOS - 2 - i)) / 2) i++;
        int j = t - (i * (2 * MPOS - 1 - i)) / 2 + i + 1;

        for (int k = tid; k < NB * NB; k += 256) hist[k] = 0;
        __syncthreads();

        // 2048 samples / 256 threads = 8 each; 441-bin hist, no predicates
        const uint2* colA = (const uint2*)&g_msaT[(size_t)i * NSEQ];
        const uint2* colB = (const uint2*)&g_msaT[(size_t)j * NSEQ];
        uint2 va = colA[tid];
        uint2 vb = colB[tid];
        #pragma unroll
        for (int b = 0; b < 4; b++) {
            int a0 = (va.x >> (8 * b)) & 0xFF, b0 = (vb.x >> (8 * b)) & 0xFF;
            atomicAdd(&hist[a0 * NB + b0], 1);
        }
        #pragma unroll
        for (int b = 0; b < 4; b++) {
            int a0 = (va.y >> (8 * b)) & 0xFF, b0 = (vb.y >> (8 * b)) & 0xFF;
            atomicAdd(&hist[a0 * NB + b0], 1);
        }
        __syncthreads();

        // mi*tot = Sum c*log2c + tot*log2tot - Sum ci*log2ci - Sum cj*log2cj
        // warp0: row marginals + tot; warp1: col marginals; warps2-7: bin sweep.
        float s = 0.0f;
        if (wid == 0) {
            int ci = 0;
            if (lane < N_AA) {
                #pragma unroll
                for (int b = 0; b < N_AA; b++) ci += hist[lane * NB + b];
                s -= (float)ci * g_log2tab[ci];
            }
            int tot = ci;
            #pragma unroll
            for (int off = 16; off; off >>= 1)
                tot += __shfl_xor_sync(0xFFFFFFFFu, tot, off);
            if (lane == 0) {
                s += (float)tot * g_log2tab[tot];
                sh_tot = tot;
            }
        } else if (wid == 1) {
            if (lane < N_AA) {
                int cj = 0;
                #pragma unroll
                for (int a = 0; a < N_AA; a++) cj += hist[a * NB + lane];  // stride 21: conflict-free
                s -= (float)cj * g_log2tab[cj];
            }
        } else {
            for (int k = tid - 64; k < NB * NB; k += 192) {
                int a = k / NB, b = k - a * NB;
                if (a < N_AA && b < N_AA) {
                    int c = hist[k];
                    s += (float)c * g_log2tab[c];      // log2tab[0]=0 -> no branch
                }
            }
        }

        #pragma unroll
        for (int off = 16; off; off >>= 1)
            s += __shfl_down_sync(0xFFFFFFFFu, s, off);
        if (lane == 0) warp_red[wid] = s;
        __syncthreads();
        if (tid == 0) {
            float S = 0.0f;
            #pragma unroll
            for (int wq = 0; wq < 8; wq++) S += warp_red[wq];
            int   tot = sh_tot;
            float mi  = (tot > 0) ? (S / (float)tot) : 0.0f;
            out_mi[i * SLEN + j] = mi;
            out_mi[j * SLEN + i] = mi;
        }
    }
}

// ---------------------------------------------------------------------------
extern "C" void kernel_launch(void* const* d_in, const int* in_sizes, int n_in,
                              void* d_out, int out_size) {
    const int*   msa = nullptr;
    const float* pc  = nullptr;
    for (int k = 0; k < n_in; k++) {
        if (in_sizes[k] == NSEQ * SLEN) msa = (const int*)d_in[k];
        else if (in_sizes[k] == 1)      pc  = (const float*)d_in[k];
    }
    float* out      = (float*)d_out;
    float* out_pssm = out;                          // [512][20]
    float* out_cons = out + SLEN * N_AA;            // [512]
    float* out_mi   = out + SLEN * N_AA + SLEN;     // [512][512]

    k_all<<<GRID, 256>>>(msa, pc, out_pssm, out_cons, out_mi);
}

// round 13
// speedup vs baseline: 1.1050x; 1.1050x over previous
#include <cuda_runtime.h>
#include <stdint.h>
#include <math.h>

#define N_AA   20
#define NB     21                        // histogram side (incl. gap symbol)
#define NSEQ   2048
#define SLEN   512
#define MPOS   100
#define NPAIR  (MPOS * (MPOS - 1) / 2)   // 4950 packed upper-triangle pairs
#define NBLK   (NPAIR + SLEN)            // + 512 stats/zero-fill blocks

// Scratch (allocation-free rule: __device__ globals)
__device__ uint8_t g_msaT[SLEN * NSEQ];       // 1 MB, transposed msa as u8
__device__ float   g_log2tab[NSEQ + 1];       // log2(c) for integer counts

// -------------------- launch 1: transpose msa -> u8 [i][n], + log2 table ----
__global__ void k_transpose_init(const int* __restrict__ msa) {
    __shared__ uint8_t tile[32][33];
    int i0 = blockIdx.x * 32;
    int n0 = blockIdx.y * 32;
    int tx = threadIdx.x, ty = threadIdx.y;

    // fold log2-table init into the first 3 blocks of column 0
    if (blockIdx.x == 0 && blockIdx.y < 3) {
        int idx = blockIdx.y * 1024 + ty * 32 + tx;
        if (idx <= NSEQ) g_log2tab[idx] = (idx == 0) ? 0.0f : log2f((float)idx);
    }

    tile[ty][tx] = (uint8_t)msa[(n0 + ty) * SLEN + (i0 + tx)];   // coalesced read
    __syncthreads();
    g_msaT[(size_t)(i0 + ty) * NSEQ + (n0 + tx)] = tile[tx][ty]; // coalesced write
}

// -------------------- launch 2: streaming grid, one work item per block -----
__global__ void __launch_bounds__(256) k_main(const float* __restrict__ pc,
                                              float* __restrict__ out_pssm,
                                              float* __restrict__ out_cons,
                                              float* __restrict__ out_mi) {
    __shared__ int   hist[NB * NB];
    __shared__ float warp_red[8];
    __shared__ int   sh_tot;

    int bx   = blockIdx.x;
    int tid  = threadIdx.x;
    int lane = tid & 31;
    int wid  = tid >> 5;

    if (bx >= NPAIR) {
        // ---------------- stats + zero-fill role: position r ----------------
        int r = bx - NPAIR;

        // zero the non-MI part of MI-canvas row r, and the diagonal cell
        {
            int     c0   = (r < MPOS) ? MPOS : 0;
            float4* rowp = (float4*)(out_mi + r * SLEN + c0);
            int     n4   = (SLEN - c0) >> 2;
            float4  z4   = make_float4(0.f, 0.f, 0.f, 0.f);
            for (int k = tid; k < n4; k += 256) rowp[k] = z4;
            if (tid == 0 && r < MPOS) out_mi[r * SLEN + r] = 0.0f;
        }

        if (tid < NB) hist[tid] = 0;
        __syncthreads();

        // 2048 samples / 256 threads = one uint2 (8 samples) per thread
        const uint2* col = (const uint2*)&g_msaT[(size_t)r * NSEQ];
        uint2 v = col[tid];
        #pragma unroll
        for (int b = 0; b < 4; b++) atomicAdd(&hist[(v.x >> (8 * b)) & 0xFF], 1);
        #pragma unroll
        for (int b = 0; b < 4; b++) atomicAdd(&hist[(v.y >> (8 * b)) & 0xFF], 1);
        __syncthreads();

        if (tid < 32) {
            int c   = (tid < N_AA) ? hist[tid] : 0;
            int tot = c;
            #pragma unroll
            for (int off = 16; off; off >>= 1)
                tot += __shfl_xor_sync(0xFFFFFFFFu, tot, off);

            float e = 0.0f;
            if (tid < N_AA) {
                float pcv  = 0.01f * pc[0];
                float cf   = (float)c;
                float freq = (cf + pcv) / ((float)NSEQ + pcv * (float)N_AA);
                out_pssm[r * N_AA + tid] = logf(freq * (float)N_AA + 1e-10f);
                float f = cf / fmaxf((float)tot, 1.0f);
                e = f * log2f(f + 1e-10f);
            }
            #pragma unroll
            for (int off = 16; off; off >>= 1)
                e += __shfl_xor_sync(0xFFFFFFFFu, e, off);
            if (tid == 0)
                out_cons[r] = (tot > 0) ? (1.0f + e / 4.321928094887363f) : 0.0f;
        }
        return;
    }

    // ---------------- MI pair role: decode packed upper-triangle ------------
    int t = bx;
    int i = (int)((2.0f * MPOS - 1.0f
                   - sqrtf((2.0f * MPOS - 1.0f) * (2.0f * MPOS - 1.0f)
                           - 8.0f * (float)t)) * 0.5f);
    while (i > 0 && t <  (i * (2 * MPOS - 1 - i)) / 2) i--;
    while (t >= ((i + 1) * (2 * MPOS - 2 - i)) / 2) i++;
    int j = t - (i * (2 * MPOS - 1 - i)) / 2 + i + 1;

    for (int k = tid; k < NB * NB; k += 256) hist[k] = 0;
    __syncthreads();

    // 2048 samples / 256 threads = 8 each; 441-bin hist, no predicates
    const uint2* colA = (const uint2*)&g_msaT[(size_t)i * NSEQ];
    const uint2* colB = (const uint2*)&g_msaT[(size_t)j * NSEQ];
    uint2 va = colA[tid];
    uint2 vb = colB[tid];
    #pragma unroll
    for (int b = 0; b < 4; b++) {
        int a0 = (va.x >> (8 * b)) & 0xFF, b0 = (vb.x >> (8 * b)) & 0xFF;
        atomicAdd(&hist[a0 * NB + b0], 1);
    }
    #pragma unroll
    for (int b = 0; b < 4; b++) {
        int a0 = (va.y >> (8 * b)) & 0xFF, b0 = (vb.y >> (8 * b)) & 0xFF;
        atomicAdd(&hist[a0 * NB + b0], 1);
    }
    __syncthreads();

    // mi*tot = Sum c*log2c + tot*log2tot - Sum ci*log2ci - Sum cj*log2cj
    // warp0: row marginals + tot; warp1: col marginals; warps2-7: bin sweep.
    float s = 0.0f;
    if (wid == 0) {
        int ci = 0;
        if (lane < N_AA) {
            #pragma unroll
            for (int b = 0; b < N_AA; b++) ci += hist[lane * NB + b];
            s -= (float)ci * g_log2tab[ci];
        }
        int tot = ci;
        #pragma unroll
        for (int off = 16; off; off >>= 1)
            tot += __shfl_xor_sync(0xFFFFFFFFu, tot, off);
        if (lane == 0) {
            s += (float)tot * g_log2tab[tot];
            sh_tot = tot;
        }
    } else if (wid == 1) {
        if (lane < N_AA) {
            int cj = 0;
            #pragma unroll
            for (int a = 0; a < N_AA; a++) cj += hist[a * NB + lane];  // stride 21: conflict-free
            s -= (float)cj * g_log2tab[cj];
        }
    } else {
        for (int k = tid - 64; k < NB * NB; k += 192) {
            int a = k / NB, b = k - a * NB;
            if (a < N_AA && b < N_AA) {
                int c = hist[k];
                s += (float)c * g_log2tab[c];      // log2tab[0]=0 -> no branch
            }
        }
    }

    #pragma unroll
    for (int off = 16; off; off >>= 1)
        s += __shfl_down_sync(0xFFFFFFFFu, s, off);
    if (lane == 0) warp_red[wid] = s;
    __syncthreads();
    if (tid == 0) {
        float S = 0.0f;
        #pragma unroll
        for (int wq = 0; wq < 8; wq++) S += warp_red[wq];
        int   tot = sh_tot;
        float mi  = (tot > 0) ? (S / (float)tot) : 0.0f;
        out_mi[i * SLEN + j] = mi;
        out_mi[j * SLEN + i] = mi;
    }
}

// ---------------------------------------------------------------------------
extern "C" void kernel_launch(void* const* d_in, const int* in_sizes, int n_in,
                              void* d_out, int out_size) {
    const int*   msa = nullptr;
    const float* pc  = nullptr;
    for (int k = 0; k < n_in; k++) {
        if (in_sizes[k] == NSEQ * SLEN) msa = (const int*)d_in[k];
        else if (in_sizes[k] == 1)      pc  = (const float*)d_in[k];
    }
    float* out      = (float*)d_out;
    float* out_pssm = out;                          // [512][20]
    float* out_cons = out + SLEN * N_AA;            // [512]
    float* out_mi   = out + SLEN * N_AA + SLEN;     // [512][512]

    k_transpose_init<<<dim3(SLEN / 32, NSEQ / 32), dim3(32, 32)>>>(msa);
    k_main<<<NBLK, 256>>>(pc, out_pssm, out_cons, out_mi);
}